// round 12
// baseline (speedup 1.0000x reference)
#include <cuda_runtime.h>
#include <math.h>

#define D      256
#define MROWS  32768      // B*C = 64*512
#define BM     128
#define BN     128
#define BK     16
#define TM     8
#define TN     8
#define EPS    1e-5f

// ---------------- scratch (device globals: no allocation allowed) ----------
__device__ float g_x0[(size_t)MROWS * D];   // ping
__device__ float g_x1[(size_t)MROWS * D];   // pong
__device__ float g_Wp[D * D];               // BN-folded weight for next layer
__device__ float g_bp[D];                   // BN-folded bias
__device__ float g_sum[D];                  // column sums   (BN stats)
__device__ float g_sumsq[D];                // column sumsq  (BN stats)
__device__ float g_scale[D];                // gamma * rsqrt(var+eps)
__device__ float g_shift[D];                // beta - mu*scale

__device__ __forceinline__ float gelu_exact(float x) {
    // exact GELU: x * Phi(x) = 0.5*x*erfc(-x/sqrt(2))
    return 0.5f * x * erfcf(-0.70710678118654752440f * x);
}

// ---------------- tiny helper kernels --------------------------------------
__global__ void zero_stats_kernel() {
    int t = threadIdx.x;
    g_sum[t]   = 0.0f;
    g_sumsq[t] = 0.0f;
}

__global__ void bn_scale_kernel(const float* __restrict__ g,
                                const float* __restrict__ be) {
    int c = threadIdx.x;
    const float inv = 1.0f / (float)MROWS;
    float mu  = g_sum[c] * inv;
    float var = g_sumsq[c] * inv - mu * mu;
    float s   = g[c] * rsqrtf(var + EPS);
    g_scale[c] = s;
    g_shift[c] = be[c] - mu * s;
    g_sum[c]   = 0.0f;   // re-arm stats for the next layer
    g_sumsq[c] = 0.0f;
}

// blocks 0..D-1: W'[k][:] = scale[k]*W[k][:]; block D: b'[n] = b[n] + shift·W[:,n]
__global__ void bn_fold_kernel(const float* __restrict__ W,
                               const float* __restrict__ b) {
    int n = threadIdx.x;
    if (blockIdx.x < D) {
        int k = blockIdx.x;
        g_Wp[k * D + n] = g_scale[k] * W[k * D + n];
    } else {
        float acc = b[n];
        #pragma unroll 8
        for (int k = 0; k < D; k++)
            acc = fmaf(g_shift[k], W[k * D + n], acc);
        g_bp[n] = acc;
    }
}

// ---------------- fused GEMM + bias + GELU (+ BN stats) --------------------
// SRC: 0 = g_x0, 1 = g_x1, 2 = gather from ext_in via ids
// DST: 0 = g_x0, 1 = g_x1, 2 = ext_out
// WFOLD: use g_Wp/g_bp instead of Wparam/bparam
// STATS: accumulate column sum/sumsq of the GELU output into g_sum/g_sumsq
template<int SRC, int DST, bool WFOLD, bool STATS>
__global__ __launch_bounds__(256, 2)
void gemm_gelu_kernel(const float* __restrict__ ext_in,
                      const int*   __restrict__ ids,
                      const float* __restrict__ Wparam,
                      const float* __restrict__ bparam,
                      float*       __restrict__ ext_out)
{
    constexpr bool GATHER = (SRC == 2);
    const float* __restrict__ A    = (SRC == 0) ? g_x0 : (SRC == 1) ? g_x1 : ext_in;
    float*       __restrict__ Out  = (DST == 0) ? g_x0 : (DST == 1) ? g_x1 : ext_out;
    const float* __restrict__ W    = WFOLD ? g_Wp : Wparam;
    const float* __restrict__ bias = WFOLD ? g_bp : bparam;

    __shared__ __align__(16) float As[2][BK][BM + 4];  // K-transposed A tile
    __shared__ __align__(16) float Ws[2][BK][BN];      // natural W tile
    __shared__ int   sIds[BM];
    __shared__ float sStat[2 * BN];                    // [0:128) sum, [128:256) sumsq

    const int tid = threadIdx.x;
    const int tx  = tid & 15;
    const int ty  = tid >> 4;
    const int m0  = blockIdx.y * BM;
    const int n0  = blockIdx.x * BN;

    sStat[tid] = 0.0f;
    if (GATHER) {
        if (tid < BM) sIds[tid] = ids[m0 + tid];
        __syncthreads();
    }

    // ---- global load lane mapping ----
    const int arow = tid >> 2;           // 0..63  (+64 on second pass)
    const int ac4  = (tid & 3) << 2;     // K-offset within BK: 0,4,8,12
    const int wkr  = tid >> 5;           // 0..7   (+8 on second pass)
    const int wc4  = (tid & 31) << 2;    // N-offset within BN

    const float *aPtr0, *aPtr1;
    if (GATHER) {
        aPtr0 = A + (size_t)sIds[arow]      * D;
        aPtr1 = A + (size_t)sIds[arow + 64] * D;
    } else {
        aPtr0 = A + (size_t)(m0 + arow)      * D;
        aPtr1 = A + (size_t)(m0 + arow + 64) * D;
    }
    const float* wPtr0 = W + (size_t)wkr       * D + n0 + wc4;
    const float* wPtr1 = W + (size_t)(wkr + 8) * D + n0 + wc4;

    float4 aReg[2], wReg[2];

    auto loadGlobal = [&](int s) {
        const int k0 = s * BK;
        aReg[0] = *reinterpret_cast<const float4*>(aPtr0 + k0 + ac4);
        aReg[1] = *reinterpret_cast<const float4*>(aPtr1 + k0 + ac4);
        wReg[0] = *reinterpret_cast<const float4*>(wPtr0 + (size_t)k0 * D);
        wReg[1] = *reinterpret_cast<const float4*>(wPtr1 + (size_t)k0 * D);
    };
    auto storeSmem = [&](int buf) {
        As[buf][ac4 + 0][arow]      = aReg[0].x;
        As[buf][ac4 + 1][arow]      = aReg[0].y;
        As[buf][ac4 + 2][arow]      = aReg[0].z;
        As[buf][ac4 + 3][arow]      = aReg[0].w;
        As[buf][ac4 + 0][arow + 64] = aReg[1].x;
        As[buf][ac4 + 1][arow + 64] = aReg[1].y;
        As[buf][ac4 + 2][arow + 64] = aReg[1].z;
        As[buf][ac4 + 3][arow + 64] = aReg[1].w;
        *reinterpret_cast<float4*>(&Ws[buf][wkr][wc4])     = wReg[0];
        *reinterpret_cast<float4*>(&Ws[buf][wkr + 8][wc4]) = wReg[1];
    };

    float acc[TM][TN];
    #pragma unroll
    for (int i = 0; i < TM; i++)
        #pragma unroll
        for (int j = 0; j < TN; j++) acc[i][j] = 0.0f;

    loadGlobal(0);
    storeSmem(0);
    __syncthreads();

    const int NSTAGE = D / BK;   // 16
    #pragma unroll 1
    for (int s = 0; s < NSTAGE; s++) {
        const int buf = s & 1;
        if (s + 1 < NSTAGE) loadGlobal(s + 1);

        #pragma unroll
        for (int k = 0; k < BK; k++) {
            float a[TM], w[TN];
            *reinterpret_cast<float4*>(&a[0]) =
                *reinterpret_cast<const float4*>(&As[buf][k][ty * TM]);
            *reinterpret_cast<float4*>(&a[4]) =
                *reinterpret_cast<const float4*>(&As[buf][k][ty * TM + 4]);
            // split columns: tx*4 and 64+tx*4 -> contiguous 128B per LDS.128 phase
            *reinterpret_cast<float4*>(&w[0]) =
                *reinterpret_cast<const float4*>(&Ws[buf][k][(tx << 2)]);
            *reinterpret_cast<float4*>(&w[4]) =
                *reinterpret_cast<const float4*>(&Ws[buf][k][64 + (tx << 2)]);
            #pragma unroll
            for (int i = 0; i < TM; i++)
                #pragma unroll
                for (int j = 0; j < TN; j++)
                    acc[i][j] = fmaf(a[i], w[j], acc[i][j]);
        }

        if (s + 1 < NSTAGE) {
            __syncthreads();
            storeSmem(buf ^ 1);
            __syncthreads();
        }
    }

    // ---- epilogue: bias + exact GELU + store (+ BN stats) ----
    const int c0 = n0 + (tx << 2);
    float bv[TN];
    #pragma unroll
    for (int j = 0; j < 4; j++) {
        bv[j]     = bias[c0 + j];
        bv[4 + j] = bias[c0 + 64 + j];
    }

    float csum[TN], csq[TN];
    #pragma unroll
    for (int j = 0; j < TN; j++) { csum[j] = 0.0f; csq[j] = 0.0f; }

    #pragma unroll
    for (int i = 0; i < TM; i++) {
        const int r = m0 + ty * TM + i;
        float v[TN];
        #pragma unroll
        for (int j = 0; j < TN; j++) {
            float t = gelu_exact(acc[i][j] + bv[j]);
            v[j] = t;
            if (STATS) { csum[j] += t; csq[j] += t * t; }
        }
        *reinterpret_cast<float4*>(Out + (size_t)r * D + c0) =
            make_float4(v[0], v[1], v[2], v[3]);
        *reinterpret_cast<float4*>(Out + (size_t)r * D + c0 + 64) =
            make_float4(v[4], v[5], v[6], v[7]);
    }

    if (STATS) {
        #pragma unroll
        for (int j = 0; j < 4; j++) {
            atomicAdd(&sStat[(tx << 2) + j],            csum[j]);
            atomicAdd(&sStat[64 + (tx << 2) + j],       csum[4 + j]);
            atomicAdd(&sStat[128 + (tx << 2) + j],      csq[j]);
            atomicAdd(&sStat[128 + 64 + (tx << 2) + j], csq[4 + j]);
        }
        __syncthreads();
        if (tid < BN) atomicAdd(&g_sum[n0 + tid],         sStat[tid]);
        else          atomicAdd(&g_sumsq[n0 + tid - BN],  sStat[tid]);
    }
}

// ---------------- launcher --------------------------------------------------
extern "C" void kernel_launch(void* const* d_in, const int* in_sizes, int n_in,
                              void* d_out, int out_size)
{
    const int*   ids   = (const int*)  d_in[0];
    const float* table = (const float*)d_in[1];
    const float* W1 = (const float*)d_in[2];  const float* b1 = (const float*)d_in[3];
    const float* W2 = (const float*)d_in[4];  const float* b2 = (const float*)d_in[5];
    const float* W3 = (const float*)d_in[6];  const float* b3 = (const float*)d_in[7];
    const float* W4 = (const float*)d_in[8];  const float* b4 = (const float*)d_in[9];
    const float* g1 = (const float*)d_in[10]; const float* be1 = (const float*)d_in[11];
    const float* g2 = (const float*)d_in[12]; const float* be2 = (const float*)d_in[13];
    const float* g3 = (const float*)d_in[14]; const float* be3 = (const float*)d_in[15];
    float* out = (float*)d_out;

    dim3 grid(D / BN, MROWS / BM);   // (2, 256)
    dim3 blk(256);

    zero_stats_kernel<<<1, D>>>();

    // layer 1: gather + GEMM(W1,b1) + GELU, stats
    gemm_gelu_kernel<2, 0, false, true><<<grid, blk>>>(table, ids, W1, b1, nullptr);
    bn_scale_kernel<<<1, D>>>(g1, be1);
    bn_fold_kernel<<<D + 1, D>>>(W2, b2);

    // layer 2: x0 @ W2' + b2' (BN folded), GELU, stats
    gemm_gelu_kernel<0, 1, true, true><<<grid, blk>>>(nullptr, nullptr, nullptr, nullptr, nullptr);
    bn_scale_kernel<<<1, D>>>(g2, be2);
    bn_fold_kernel<<<D + 1, D>>>(W3, b3);

    // layer 3
    gemm_gelu_kernel<1, 0, true, true><<<grid, blk>>>(nullptr, nullptr, nullptr, nullptr, nullptr);
    bn_scale_kernel<<<1, D>>>(g3, be3);
    bn_fold_kernel<<<D + 1, D>>>(W4, b4);

    // layer 4: final GEMM + GELU -> d_out, no stats
    gemm_gelu_kernel<0, 2, true, false><<<grid, blk>>>(nullptr, nullptr, nullptr, nullptr, out);
}

// round 16
// speedup vs baseline: 1.5406x; 1.5406x over previous
#include <cuda_runtime.h>
#include <cuda_bf16.h>
#include <math.h>
#include <stdint.h>

#define D       256
#define MROWS   32768        // B*C
#define EPS     1e-5f
#define BM      128
#define BN      64
#define BK      16
#define NCHUNK  (D / BK)     // 16
#define ARB     48           // smem A row bytes: 16 bf16 = 32B data + 16B pad
#define BRB     48           // smem B row bytes

// ---------------- device scratch (no allocation allowed) -------------------
__device__ float g_x0[(size_t)MROWS * D];
__device__ float g_x1[(size_t)MROWS * D];
__device__ __nv_bfloat16 g_wh[4 * D * D];   // W^T hi, per layer, [n][k]
__device__ __nv_bfloat16 g_wl[4 * D * D];   // W^T lo
__device__ float g_sum[D], g_sumsq[D], g_scale[D], g_shift[D];

// ---------------- helpers ---------------------------------------------------
__device__ __forceinline__ uint32_t smem_u32(const void* p) {
    uint32_t r;
    asm("{ .reg .u64 t; cvta.to.shared.u64 t, %1; cvt.u32.u64 %0, t; }"
        : "=r"(r) : "l"(p));
    return r;
}
__device__ __forceinline__ float gelu_exact(float x) {
    return 0.5f * x * erfcf(-0.70710678118654752440f * x);
}
__device__ __forceinline__ void ldsm4(uint32_t* r, uint32_t a) {
    asm volatile("ldmatrix.sync.aligned.m8n8.x4.shared.b16 {%0,%1,%2,%3}, [%4];"
                 : "=r"(r[0]), "=r"(r[1]), "=r"(r[2]), "=r"(r[3]) : "r"(a));
}
__device__ __forceinline__ void mma16816(float* d, const uint32_t* a,
                                         uint32_t b0, uint32_t b1) {
    asm volatile("mma.sync.aligned.m16n8k16.row.col.f32.bf16.bf16.f32 "
                 "{%0,%1,%2,%3}, {%4,%5,%6,%7}, {%8,%9}, {%0,%1,%2,%3};"
                 : "+f"(d[0]), "+f"(d[1]), "+f"(d[2]), "+f"(d[3])
                 : "r"(a[0]), "r"(a[1]), "r"(a[2]), "r"(a[3]), "r"(b0), "r"(b1));
}
__device__ __forceinline__ uint32_t pack_bf16(__nv_bfloat16 lo, __nv_bfloat16 hi) {
    return ((uint32_t)__bfloat16_as_ushort(hi) << 16) | __bfloat16_as_ushort(lo);
}

// ---------------- tiny kernels ----------------------------------------------
__global__ void zero_stats_kernel() {
    g_sum[threadIdx.x] = 0.0f;
    g_sumsq[threadIdx.x] = 0.0f;
}

__global__ void bn_scale_kernel(const float* __restrict__ g,
                                const float* __restrict__ be) {
    int c = threadIdx.x;
    const float inv = 1.0f / (float)MROWS;
    float mu  = g_sum[c] * inv;
    float var = g_sumsq[c] * inv - mu * mu;
    float s   = g[c] * rsqrtf(var + EPS);
    g_scale[c] = s;
    g_shift[c] = be[c] - mu * s;
    g_sum[c] = 0.0f;
    g_sumsq[c] = 0.0f;
}

// transpose + hi/lo bf16 split of all 4 weight matrices: Wt[n][k] = W[k][n]
__global__ void prep_w_kernel(const float* __restrict__ W1, const float* __restrict__ W2,
                              const float* __restrict__ W3, const float* __restrict__ W4) {
    const float* W = (blockIdx.y == 0) ? W1 : (blockIdx.y == 1) ? W2
                     : (blockIdx.y == 2) ? W3 : W4;
    int k = blockIdx.x, n = threadIdx.x;
    float v = W[k * D + n];
    __nv_bfloat16 h = __float2bfloat16(v);
    float lo = v - __bfloat162float(h);
    size_t o = (size_t)blockIdx.y * D * D + (size_t)n * D + k;
    g_wh[o] = h;
    g_wl[o] = __float2bfloat16(lo);
}

// ---------------- shared layout (static: <=48KB, no attrs needed) ----------
struct __align__(16) SmemLayout {
    char  A[2][2][BM * ARB];   // [buf][hi/lo]  2*2*6144 = 24576
    char  B[2][2][BN * BRB];   // [buf][hi/lo]  2*2*3072 = 12288
    float bias[BN];
    float scale[D];
    float shift[D];
    int   ids[BM];
    float stat[2 * BN];
};

// ---------------- fused GEMM(3x bf16 mma) + affine-A + bias + GELU + stats --
// SRC: 0=g_x0, 1=g_x1, 2=gather(table, ids)   DST: 0=g_x0, 1=g_x1, 2=ext_out
template<int SRC, int DST, bool AFFINE, bool STATS>
__global__ __launch_bounds__(256, 2)
void layer_kernel(const float* __restrict__ table, const int* __restrict__ ids,
                  int layer, const float* __restrict__ bias,
                  float* __restrict__ ext_out)
{
    __shared__ SmemLayout sm;

    const float* __restrict__ Asrc = (SRC == 0) ? g_x0 : (SRC == 1) ? g_x1 : table;
    float*       __restrict__ Out  = (DST == 0) ? g_x0 : (DST == 1) ? g_x1 : ext_out;
    const __nv_bfloat16* __restrict__ WhP = g_wh + (size_t)layer * D * D;
    const __nv_bfloat16* __restrict__ WlP = g_wl + (size_t)layer * D * D;

    const int tid = threadIdx.x, lane = tid & 31, wid = tid >> 5;
    const int wm = wid & 3, wn = wid >> 2;          // warp grid 4(m) x 2(n)
    const int m0 = blockIdx.y * BM, n0 = blockIdx.x * BN;

    if (tid < BN) sm.bias[tid] = bias[n0 + tid];
    if (AFFINE) { sm.scale[tid] = g_scale[tid]; sm.shift[tid] = g_shift[tid]; }
    if (SRC == 2 && tid < BM) sm.ids[tid] = ids[m0 + tid];
    if (STATS && tid < 2 * BN) sm.stat[tid] = 0.0f;
    __syncthreads();

    // ---- global A mapping: row = tid>>1, k-half = (tid&1)*8 floats ----
    const int ar = tid >> 1, ah = tid & 1;
    const int grow = (SRC == 2) ? sm.ids[ar] : (m0 + ar);
    const float4* __restrict__ aG = (const float4*)(Asrc + (size_t)grow * D + ah * 8);

    // ---- global B mapping: tids 0-127 load hi part, 128-255 lo part ----
    const int bt = tid & 127;
    const int bn_ = bt >> 1, bc = bt & 1;
    const __nv_bfloat16* __restrict__ bG =
        ((tid < 128) ? WhP : WlP) + (size_t)(n0 + bn_) * D + bc * 8;

    char* aStH = &sm.A[0][0][ar * ARB + ah * 16];
    char* aStL = &sm.A[0][1][ar * ARB + ah * 16];
    char* bSt  = &sm.B[0][(tid < 128) ? 0 : 1][bn_ * BRB + bc * 16];

    // ---- ldmatrix base addresses (buf 0) ----
    uint32_t aRd0, bRd0;
    {
        const int rlo = (lane & 7) + ((lane >> 3) & 1) * 8;
        const int kb  = ((lane >> 4) & 1) * 16;
        aRd0 = smem_u32(&sm.A[0][0][0]) + (wm * 32 + rlo) * ARB + kb;
        bRd0 = smem_u32(&sm.B[0][0][0]) + (wn * 32 + rlo) * BRB + kb;
    }

    float4 aR0, aR1; uint4 bR;
    auto loadG = [&](int c) {
        aR0 = aG[c * 4];
        aR1 = aG[c * 4 + 1];
        bR  = *(const uint4*)(bG + c * 16);
    };
    auto storeS = [&](int buf, int c) {
        float v[8];
        *(float4*)&v[0] = aR0; *(float4*)&v[4] = aR1;
        const int kb = c * 16 + ah * 8;
        uint32_t hw[4], lw[4];
        #pragma unroll
        for (int j = 0; j < 4; j++) {
            float x0 = v[2 * j], x1 = v[2 * j + 1];
            if (AFFINE) {
                x0 = fmaf(x0, sm.scale[kb + 2 * j],     sm.shift[kb + 2 * j]);
                x1 = fmaf(x1, sm.scale[kb + 2 * j + 1], sm.shift[kb + 2 * j + 1]);
            }
            __nv_bfloat16 h0 = __float2bfloat16(x0), h1 = __float2bfloat16(x1);
            __nv_bfloat16 l0 = __float2bfloat16(x0 - __bfloat162float(h0));
            __nv_bfloat16 l1 = __float2bfloat16(x1 - __bfloat162float(h1));
            hw[j] = pack_bf16(h0, h1);
            lw[j] = pack_bf16(l0, l1);
        }
        *(uint4*)(aStH + buf * (int)sizeof(sm.A[0])) = make_uint4(hw[0], hw[1], hw[2], hw[3]);
        *(uint4*)(aStL + buf * (int)sizeof(sm.A[0])) = make_uint4(lw[0], lw[1], lw[2], lw[3]);
        *(uint4*)(bSt  + buf * (int)sizeof(sm.B[0])) = bR;
    };

    float acc[2][4][4];
    #pragma unroll
    for (int i = 0; i < 2; i++)
        #pragma unroll
        for (int j = 0; j < 4; j++)
            #pragma unroll
            for (int k = 0; k < 4; k++) acc[i][j][k] = 0.0f;

    loadG(0);
    storeS(0, 0);
    __syncthreads();

    #pragma unroll 1
    for (int c = 0; c < NCHUNK; c++) {
        const int buf = c & 1;
        if (c + 1 < NCHUNK) loadG(c + 1);

        uint32_t aH[2][4], aL[2][4], bH[2][4], bL[2][4];
        const uint32_t aB = aRd0 + buf * (uint32_t)sizeof(sm.A[0]);
        const uint32_t bB = bRd0 + buf * (uint32_t)sizeof(sm.B[0]);
        #pragma unroll
        for (int mi = 0; mi < 2; mi++) {
            ldsm4(aH[mi], aB + mi * (16 * ARB));
            ldsm4(aL[mi], aB + mi * (16 * ARB) + BM * ARB);
        }
        #pragma unroll
        for (int p = 0; p < 2; p++) {
            ldsm4(bH[p], bB + p * (16 * BRB));
            ldsm4(bL[p], bB + p * (16 * BRB) + BN * BRB);
        }

        // 3-pass split-bf16: Ah*Bh + Ah*Bl + Al*Bh  (Al*Bl ~2^-18, dropped)
        #pragma unroll
        for (int mi = 0; mi < 2; mi++)
            #pragma unroll
            for (int p = 0; p < 2; p++) {
                mma16816(acc[mi][2 * p],     aH[mi], bH[p][0], bH[p][2]);
                mma16816(acc[mi][2 * p + 1], aH[mi], bH[p][1], bH[p][3]);
                mma16816(acc[mi][2 * p],     aH[mi], bL[p][0], bL[p][2]);
                mma16816(acc[mi][2 * p + 1], aH[mi], bL[p][1], bL[p][3]);
                mma16816(acc[mi][2 * p],     aL[mi], bH[p][0], bH[p][2]);
                mma16816(acc[mi][2 * p + 1], aL[mi], bH[p][1], bH[p][3]);
            }

        if (c + 1 < NCHUNK) {
            __syncthreads();
            storeS(buf ^ 1, c + 1);
            __syncthreads();
        }
    }

    // ---- epilogue: bias + exact GELU + store (+ BN column stats) ----
    const int g = lane >> 2, t4 = lane & 3;
    float s_[4][2], q_[4][2];
    if (STATS) {
        #pragma unroll
        for (int ni = 0; ni < 4; ni++) { s_[ni][0] = s_[ni][1] = 0.f; q_[ni][0] = q_[ni][1] = 0.f; }
    }
    #pragma unroll
    for (int mi = 0; mi < 2; mi++) {
        const int row = m0 + wm * 32 + mi * 16 + g;
        #pragma unroll
        for (int ni = 0; ni < 4; ni++) {
            const int cl = wn * 32 + ni * 8 + t4 * 2;
            const float b0 = sm.bias[cl], b1 = sm.bias[cl + 1];
            float g0 = gelu_exact(acc[mi][ni][0] + b0);
            float g1 = gelu_exact(acc[mi][ni][1] + b1);
            float g2 = gelu_exact(acc[mi][ni][2] + b0);
            float g3 = gelu_exact(acc[mi][ni][3] + b1);
            *(float2*)(Out + (size_t)row * D + n0 + cl)       = make_float2(g0, g1);
            *(float2*)(Out + (size_t)(row + 8) * D + n0 + cl) = make_float2(g2, g3);
            if (STATS) {
                s_[ni][0] += g0 + g2;           s_[ni][1] += g1 + g3;
                q_[ni][0] += g0 * g0 + g2 * g2; q_[ni][1] += g1 * g1 + g3 * g3;
            }
        }
    }
    if (STATS) {
        #pragma unroll
        for (int ni = 0; ni < 4; ni++)
            #pragma unroll
            for (int j = 0; j < 2; j++) {
                float s = s_[ni][j], q = q_[ni][j];
                s += __shfl_xor_sync(0xffffffffu, s, 4);
                s += __shfl_xor_sync(0xffffffffu, s, 8);
                s += __shfl_xor_sync(0xffffffffu, s, 16);
                q += __shfl_xor_sync(0xffffffffu, q, 4);
                q += __shfl_xor_sync(0xffffffffu, q, 8);
                q += __shfl_xor_sync(0xffffffffu, q, 16);
                if (lane < 4) {
                    const int cl = wn * 32 + ni * 8 + 2 * lane + j;
                    atomicAdd(&sm.stat[cl], s);
                    atomicAdd(&sm.stat[BN + cl], q);
                }
            }
        __syncthreads();
        if (tid < BN)          atomicAdd(&g_sum[n0 + tid], sm.stat[tid]);
        else if (tid < 2 * BN) atomicAdd(&g_sumsq[n0 + tid - BN], sm.stat[tid]);
    }
}

// ---------------- launcher --------------------------------------------------
extern "C" void kernel_launch(void* const* d_in, const int* in_sizes, int n_in,
                              void* d_out, int out_size)
{
    const int*   ids   = (const int*)  d_in[0];
    const float* table = (const float*)d_in[1];
    const float* W1 = (const float*)d_in[2];  const float* b1 = (const float*)d_in[3];
    const float* W2 = (const float*)d_in[4];  const float* b2 = (const float*)d_in[5];
    const float* W3 = (const float*)d_in[6];  const float* b3 = (const float*)d_in[7];
    const float* W4 = (const float*)d_in[8];  const float* b4 = (const float*)d_in[9];
    const float* g1 = (const float*)d_in[10]; const float* be1 = (const float*)d_in[11];
    const float* g2 = (const float*)d_in[12]; const float* be2 = (const float*)d_in[13];
    const float* g3 = (const float*)d_in[14]; const float* be3 = (const float*)d_in[15];
    float* out = (float*)d_out;

    dim3 grid(D / BN, MROWS / BM);   // (4, 256) = 1024 CTAs
    dim3 blk(256);

    zero_stats_kernel<<<1, D>>>();
    prep_w_kernel<<<dim3(D, 4), D>>>(W1, W2, W3, W4);

    // L1: gather + GEMM(W1) + GELU, stats
    layer_kernel<2, 0, false, true><<<grid, blk>>>(table, ids, 0, b1, nullptr);
    bn_scale_kernel<<<1, D>>>(g1, be1);

    // L2: affine(x0) @ W2 + b2, GELU, stats
    layer_kernel<0, 1, true, true><<<grid, blk>>>(nullptr, nullptr, 1, b2, nullptr);
    bn_scale_kernel<<<1, D>>>(g2, be2);

    // L3
    layer_kernel<1, 0, true, true><<<grid, blk>>>(nullptr, nullptr, 2, b3, nullptr);
    bn_scale_kernel<<<1, D>>>(g3, be3);

    // L4 -> d_out, no stats
    layer_kernel<0, 2, true, false><<<grid, blk>>>(nullptr, nullptr, 3, b4, out);
}